// round 5
// baseline (speedup 1.0000x reference)
#include <cuda_runtime.h>
#include <cuda_fp16.h>

// BlurNet: fake_B = w * mean_k bilinear(fake_S, pix + t_k*20*blurmap) + bias
//          offsets_flat[b, 2k+c] = t_k * 20 * blurmap[b, c],  t_k = (7-k)/7
// B=8, C=3, H=W=256. Output: fake_B (B*3*H*W) then offsets (B*30*H*W), f32.
//
// smem tile fp16 with horizontal pair duplication (stride TDIM, unpadded —
// offsets are random so bank conflicts are balls-in-bins; padding proven
// useless in R4):
//   Ap[i] = (c0,c1)@(r,c),(c0,c1)@(r,c+1)  8B -> LDS.64
//   Cp[i] = (c2)@(r,c),(c2)@(r,c+1)        4B -> LDS.32
// Halo fill vectorized: 4 entries/thread from one float4 + one scalar LDG
// per channel (alignment holds because tx0-HALO+4q == 0 mod 4).

#define H 256
#define W 256
#define HW (H * W)
#define BATCH 8
#define TILE 32
#define HALO 20
#define TDIM (TILE + 2 * HALO)   // 72
#define NTHREADS 256

__global__ __launch_bounds__(NTHREADS, 3)
void blurnet_kernel(const float* __restrict__ fake_S,
                    const float* __restrict__ blurmap,
                    const float* __restrict__ weight,
                    const float* __restrict__ bias,
                    float* __restrict__ out_fb,
                    float* __restrict__ out_off)
{
    extern __shared__ __align__(16) unsigned char smem_raw[];
    uint2*   Ap = (uint2*)smem_raw;                          // 72*72*8 = 41472 B
    __half2* Cp = (__half2*)(smem_raw + TDIM * TDIM * 8);    // 72*72*4 = 20736 B

    const int tx0 = blockIdx.x * TILE;
    const int ty0 = blockIdx.y * TILE;
    const int b   = blockIdx.z;
    const int tid = threadIdx.x;

    const float* img  = fake_S  + (size_t)b * 3 * HW;
    const float* bm   = blurmap + (size_t)b * 2 * HW;
    float*       fb   = out_fb  + (size_t)b * 3 * HW;
    float*       offp = out_off + (size_t)b * 30 * HW;

    // ---- Phase 1: halo fill, 4 dup-entries per thread-group ----
    // Entry i stores pixels (i, i+1); group of 4 entries needs 5 px -> one
    // aligned float4 + one scalar per channel.
    const int GROUPS = TDIM * (TDIM / 4);   // 72 * 18 = 1296
    #pragma unroll 2
    for (int g = tid; g < GROUPS; g += NTHREADS) {
        int r   = g / (TDIM / 4);
        int q   = g - r * (TDIM / 4);
        int cc0 = q * 4;
        int gy  = ty0 - HALO + r;
        int gx0 = tx0 - HALO + cc0;        // == 0 mod 4 always

        float c0[5], c1[5], c2[5];
        #pragma unroll
        for (int j = 0; j < 5; j++) { c0[j] = 0.f; c1[j] = 0.f; c2[j] = 0.f; }

        if ((unsigned)gy < (unsigned)H) {
            if ((unsigned)gx0 < (unsigned)W) {      // fully in (mod-4 aligned)
                int gi = gy * W + gx0;
                float4 v0 = *(const float4*)(img + gi);
                float4 v1 = *(const float4*)(img + gi + HW);
                float4 v2 = *(const float4*)(img + gi + 2 * HW);
                c0[0] = v0.x; c0[1] = v0.y; c0[2] = v0.z; c0[3] = v0.w;
                c1[0] = v1.x; c1[1] = v1.y; c1[2] = v1.z; c1[3] = v1.w;
                c2[0] = v2.x; c2[1] = v2.y; c2[2] = v2.z; c2[3] = v2.w;
            }
            if ((unsigned)(gx0 + 4) < (unsigned)W) {
                int gi = gy * W + gx0 + 4;
                c0[4] = __ldg(img + gi);
                c1[4] = __ldg(img + gi + HW);
                c2[4] = __ldg(img + gi + 2 * HW);
            }
        }

        int base = r * TDIM + cc0;
        #pragma unroll
        for (int j = 0; j < 4; j++) {
            __half2 lo = __floats2half2_rn(c0[j],     c1[j]);
            __half2 hi = __floats2half2_rn(c0[j + 1], c1[j + 1]);
            uint2 w;
            w.x = *(unsigned int*)&lo;
            w.y = *(unsigned int*)&hi;
            Ap[base + j] = w;
            Cp[base + j] = __floats2half2_rn(c2[j], c2[j + 1]);
        }
    }

    // ---- Phase 2: offsets output, vectorized (4 consecutive x per thread) ----
    {
        int ry = tid >> 3;            // 0..31
        int xq = (tid & 7) * 4;       // 0,4,...,28
        int gi = (ty0 + ry) * W + tx0 + xq;
        float4 b0 = *(const float4*)(bm + gi);
        float4 b1 = *(const float4*)(bm + gi + HW);
        float4 ob0 = make_float4(20.f * b0.x, 20.f * b0.y, 20.f * b0.z, 20.f * b0.w);
        float4 ob1 = make_float4(20.f * b1.x, 20.f * b1.y, 20.f * b1.z, 20.f * b1.w);
        #pragma unroll
        for (int k = 0; k < 15; k++) {
            const float t = (float)(7 - k) / 7.0f;
            float4 oy = make_float4(t * ob0.x, t * ob0.y, t * ob0.z, t * ob0.w);
            float4 ox = make_float4(t * ob1.x, t * ob1.y, t * ob1.z, t * ob1.w);
            *(float4*)(offp + (2 * k) * HW + gi)     = oy;
            *(float4*)(offp + (2 * k + 1) * HW + gi) = ox;
        }
    }
    __syncthreads();

    const float wgt = __ldg(weight) * (1.0f / 15.0f);
    const float bs  = __ldg(bias);

    // ---- Phase 3: blur, lane = x, 4 row iterations ----
    #pragma unroll 1
    for (int i = 0; i < (TILE * TILE) / NTHREADS; i++) {
        int p  = i * NTHREADS + tid;
        int yl = p >> 5;
        int xl = p & 31;
        int gy = ty0 + yl;
        int gx = tx0 + xl;
        int gidx = gy * W + gx;

        float ob0 = 20.0f * __ldg(bm + gidx);        // dy scale (ch0)
        float ob1 = 20.0f * __ldg(bm + gidx + HW);   // dx scale (ch1)

        // k = 7 (t = 0): exact center sample
        int cbase = (yl + HALO) * TDIM + (xl + HALO);
        uint2 cw = Ap[cbase];
        float2 cl = __half22float2(*(__half2*)&cw.x);
        float2 cz = __half22float2(Cp[cbase]);
        float s0 = cl.x, s1 = cl.y, s2 = cz.x;

        #pragma unroll
        for (int k = 0; k < 15; k++) {
            if (k == 7) continue;
            const float t = (float)(7 - k) / 7.0f;   // compile-time constant
            float oy = t * ob0;
            float ox = t * ob1;

            float fy  = (float)gy + oy;              // global coords = ref rounding
            float fx  = (float)gx + ox;
            float fy0 = floorf(fy);
            float fx0 = floorf(fx);
            float tyf = fy - fy0;
            float txf = fx - fx0;
            int iy = (int)fy0 - ty0 + HALO;
            int ix = (int)fx0 - tx0 + HALO;
            int base2 = iy * TDIM + ix;

            uint2   w0 = Ap[base2];            // row y0: (c0,c1)@x0,x1
            uint2   w1 = Ap[base2 + TDIM];     // row y1
            __half2 z0 = Cp[base2];            // c2@(x0,x1), row y0
            __half2 z1 = Cp[base2 + TDIM];     // row y1

            float2 p00 = __half22float2(*(__half2*)&w0.x);
            float2 p01 = __half22float2(*(__half2*)&w0.y);
            float2 p10 = __half22float2(*(__half2*)&w1.x);
            float2 p11 = __half22float2(*(__half2*)&w1.y);
            float2 q0  = __half22float2(z0);
            float2 q1  = __half22float2(z1);

            float w11f = tyf * txf;
            float w10f = tyf - w11f;
            float w01f = txf - w11f;
            float w00f = 1.0f - tyf - txf + w11f;

            s0 = fmaf(w00f, p00.x, s0); s0 = fmaf(w01f, p01.x, s0);
            s0 = fmaf(w10f, p10.x, s0); s0 = fmaf(w11f, p11.x, s0);
            s1 = fmaf(w00f, p00.y, s1); s1 = fmaf(w01f, p01.y, s1);
            s1 = fmaf(w10f, p10.y, s1); s1 = fmaf(w11f, p11.y, s1);
            s2 = fmaf(w00f, q0.x, s2);  s2 = fmaf(w01f, q0.y, s2);
            s2 = fmaf(w10f, q1.x, s2);  s2 = fmaf(w11f, q1.y, s2);
        }

        fb[gidx]          = fmaf(wgt, s0, bs);
        fb[gidx + HW]     = fmaf(wgt, s1, bs);
        fb[gidx + 2 * HW] = fmaf(wgt, s2, bs);
    }
}

extern "C" void kernel_launch(void* const* d_in, const int* in_sizes, int n_in,
                              void* d_out, int out_size)
{
    const float* fake_S  = (const float*)d_in[0];
    const float* blurmap = (const float*)d_in[1];
    const float* weight  = (const float*)d_in[2];
    const float* bias    = (const float*)d_in[3];

    float* out_fb  = (float*)d_out;
    float* out_off = (float*)d_out + (size_t)BATCH * 3 * HW;

    const int smem = TDIM * TDIM * 12;   // 62,208 B
    static bool configured = false;
    if (!configured) {
        cudaFuncSetAttribute(blurnet_kernel,
                             cudaFuncAttributeMaxDynamicSharedMemorySize, smem);
        configured = true;
    }

    dim3 grid(W / TILE, H / TILE, BATCH);   // (8, 8, 8)
    blurnet_kernel<<<grid, NTHREADS, smem>>>(fake_S, blurmap, weight, bias,
                                             out_fb, out_off);
}

// round 6
// speedup vs baseline: 1.1118x; 1.1118x over previous
#include <cuda_runtime.h>
#include <cuda_fp16.h>

// BlurNet: fake_B = w * mean_k bilinear(fake_S, pix + t_k*20*blurmap) + bias
//          offsets_flat[b, 2k+c] = t_k * 20 * blurmap[b, c],  t_k = (7-k)/7
// B=8, C=3, H=W=256. Output: fake_B (B*3*H*W) then offsets (B*30*H*W), f32.
//
// smem tile: ONE 16B entry per pixel holding both x-corners of all 3 channels
// in fp16:  [c0,c1 | c2,c0' | c1',c2' | 0,0]   (' = pixel x+1)
// => each bilinear sample = 2 LDS.128 (one per y-row). 384 thr x 2 CTAs/SM
// keeps 24 warps/SM despite the 82.9KB tile.

#define H 256
#define W 256
#define HW (H * W)
#define BATCH 8
#define TILE 32
#define HALO 20
#define TDIM (TILE + 2 * HALO)   // 72
#define NTHREADS 384

__global__ __launch_bounds__(NTHREADS, 2)
void blurnet_kernel(const float* __restrict__ fake_S,
                    const float* __restrict__ blurmap,
                    const float* __restrict__ weight,
                    const float* __restrict__ bias,
                    float* __restrict__ out_fb,
                    float* __restrict__ out_off)
{
    extern __shared__ __align__(16) uint4 tile[];   // TDIM*TDIM 16B entries

    const int tx0 = blockIdx.x * TILE;
    const int ty0 = blockIdx.y * TILE;
    const int b   = blockIdx.z;
    const int tid = threadIdx.x;

    const float* img  = fake_S  + (size_t)b * 3 * HW;
    const float* bm   = blurmap + (size_t)b * 2 * HW;
    float*       fb   = out_fb  + (size_t)b * 3 * HW;
    float*       offp = out_off + (size_t)b * 30 * HW;

    // ---- Phase 1: halo fill (R3-style scalar loads; no register arrays) ----
    #pragma unroll 2
    for (int p = tid; p < TDIM * TDIM; p += NTHREADS) {
        int r  = p / TDIM;
        int cc = p - r * TDIM;
        int gy = ty0 - HALO + r;
        int gx = tx0 - HALO + cc;
        float v0 = 0.f, v1 = 0.f, v2 = 0.f;   // (gy, gx)
        float u0 = 0.f, u1 = 0.f, u2 = 0.f;   // (gy, gx+1)
        bool rowok = (unsigned)gy < (unsigned)H;
        if (rowok && (unsigned)gx < (unsigned)W) {
            int gi = gy * W + gx;
            v0 = __ldg(img + gi);
            v1 = __ldg(img + gi + HW);
            v2 = __ldg(img + gi + 2 * HW);
        }
        if (rowok && (unsigned)(gx + 1) < (unsigned)W) {
            int gi = gy * W + gx + 1;
            u0 = __ldg(img + gi);
            u1 = __ldg(img + gi + HW);
            u2 = __ldg(img + gi + 2 * HW);
        }
        __half2 hA = __floats2half2_rn(v0, v1);   // c0,c1 @x0
        __half2 hB = __floats2half2_rn(v2, u0);   // c2@x0, c0@x1
        __half2 hC = __floats2half2_rn(u1, u2);   // c1,c2 @x1
        uint4 w;
        w.x = *(unsigned int*)&hA;
        w.y = *(unsigned int*)&hB;
        w.z = *(unsigned int*)&hC;
        w.w = 0u;
        tile[p] = w;
    }

    // ---- Phase 2: offsets output, vectorized (threads < 256 only) ----
    if (tid < 256) {
        int ry = tid >> 3;            // 0..31
        int xq = (tid & 7) * 4;       // 0,4,...,28
        int gi = (ty0 + ry) * W + tx0 + xq;
        float4 b0 = *(const float4*)(bm + gi);
        float4 b1 = *(const float4*)(bm + gi + HW);
        float4 ob0 = make_float4(20.f * b0.x, 20.f * b0.y, 20.f * b0.z, 20.f * b0.w);
        float4 ob1 = make_float4(20.f * b1.x, 20.f * b1.y, 20.f * b1.z, 20.f * b1.w);
        #pragma unroll
        for (int k = 0; k < 15; k++) {
            const float t = (float)(7 - k) / 7.0f;
            float4 oy = make_float4(t * ob0.x, t * ob0.y, t * ob0.z, t * ob0.w);
            float4 ox = make_float4(t * ob1.x, t * ob1.y, t * ob1.z, t * ob1.w);
            *(float4*)(offp + (2 * k) * HW + gi)     = oy;
            *(float4*)(offp + (2 * k + 1) * HW + gi) = ox;
        }
    }
    __syncthreads();

    const float wgt = __ldg(weight) * (1.0f / 15.0f);
    const float bs  = __ldg(bias);

    // ---- Phase 3: blur; lane = x; ~2.67 px/thread ----
    #pragma unroll 1
    for (int p = tid; p < TILE * TILE; p += NTHREADS) {
        int yl = p >> 5;
        int xl = p & 31;
        int gy = ty0 + yl;
        int gx = tx0 + xl;
        int gidx = gy * W + gx;

        float ob0 = 20.0f * __ldg(bm + gidx);        // dy scale (ch0)
        float ob1 = 20.0f * __ldg(bm + gidx + HW);   // dx scale (ch1)

        // k = 7 (t = 0): exact center sample
        uint4 cw = tile[(yl + HALO) * TDIM + (xl + HALO)];
        float2 cA = __half22float2(*(__half2*)&cw.x);
        float2 cB = __half22float2(*(__half2*)&cw.y);
        float s0 = cA.x, s1 = cA.y, s2 = cB.x;

        #pragma unroll
        for (int k = 0; k < 15; k++) {
            if (k == 7) continue;
            const float t = (float)(7 - k) / 7.0f;   // compile-time constant
            float oy = t * ob0;
            float ox = t * ob1;

            float fy  = (float)gy + oy;              // global coords = ref rounding
            float fx  = (float)gx + ox;
            float fy0 = floorf(fy);
            float fx0 = floorf(fx);
            float tyf = fy - fy0;
            float txf = fx - fx0;
            int iy = (int)fy0 - ty0 + HALO;
            int ix = (int)fx0 - tx0 + HALO;
            int base2 = iy * TDIM + ix;

            uint4 w0 = tile[base2];          // row y0: c0c1c2 @ x0,x1
            uint4 w1 = tile[base2 + TDIM];   // row y1

            float2 A0 = __half22float2(*(__half2*)&w0.x);  // c0,c1 @x0
            float2 B0 = __half22float2(*(__half2*)&w0.y);  // c2@x0, c0@x1
            float2 C0 = __half22float2(*(__half2*)&w0.z);  // c1,c2 @x1
            float2 A1 = __half22float2(*(__half2*)&w1.x);
            float2 B1 = __half22float2(*(__half2*)&w1.y);
            float2 C1 = __half22float2(*(__half2*)&w1.z);

            float w11f = tyf * txf;
            float w10f = tyf - w11f;
            float w01f = txf - w11f;
            float w00f = 1.0f - tyf - txf + w11f;

            s0 = fmaf(w00f, A0.x, s0); s0 = fmaf(w01f, B0.y, s0);
            s0 = fmaf(w10f, A1.x, s0); s0 = fmaf(w11f, B1.y, s0);
            s1 = fmaf(w00f, A0.y, s1); s1 = fmaf(w01f, C0.x, s1);
            s1 = fmaf(w10f, A1.y, s1); s1 = fmaf(w11f, C1.x, s1);
            s2 = fmaf(w00f, B0.x, s2); s2 = fmaf(w01f, C0.y, s2);
            s2 = fmaf(w10f, B1.x, s2); s2 = fmaf(w11f, C1.y, s2);
        }

        fb[gidx]          = fmaf(wgt, s0, bs);
        fb[gidx + HW]     = fmaf(wgt, s1, bs);
        fb[gidx + 2 * HW] = fmaf(wgt, s2, bs);
    }
}

extern "C" void kernel_launch(void* const* d_in, const int* in_sizes, int n_in,
                              void* d_out, int out_size)
{
    const float* fake_S  = (const float*)d_in[0];
    const float* blurmap = (const float*)d_in[1];
    const float* weight  = (const float*)d_in[2];
    const float* bias    = (const float*)d_in[3];

    float* out_fb  = (float*)d_out;
    float* out_off = (float*)d_out + (size_t)BATCH * 3 * HW;

    const int smem = TDIM * TDIM * sizeof(uint4);   // 82,944 B
    static bool configured = false;
    if (!configured) {
        cudaFuncSetAttribute(blurnet_kernel,
                             cudaFuncAttributeMaxDynamicSharedMemorySize, smem);
        configured = true;
    }

    dim3 grid(W / TILE, H / TILE, BATCH);   // (8, 8, 8)
    blurnet_kernel<<<grid, NTHREADS, smem>>>(fake_S, blurmap, weight, bias,
                                             out_fb, out_off);
}

// round 7
// speedup vs baseline: 1.2415x; 1.1166x over previous
#include <cuda_runtime.h>
#include <cuda_fp16.h>

// BlurNet: fake_B = w * mean_k bilinear(fake_S, pix + t_k*20*blurmap) + bias
//          offsets_flat[b, 2k+c] = t_k * 20 * blurmap[b, c],  t_k = (7-k)/7
// B=8, C=3, H=W=256. Output: fake_B (B*3*H*W) then offsets (B*30*H*W), f32.
//
// R7: 64x32 tiles, 512 thr, 2 CTAs/SM -> grid 256 <= capacity 296: SINGLE
// WAVE (R3's 512-tile grid at 3 CTAs/SM ran 2 waves => 58% busy; this is the
// measured bottleneck). Gather layout = proven R3 fp16 pair-dup:
//   Ap[i] = (c0,c1)@(r,c),(c0,c1)@(r,c+1)  8B -> LDS.64
//   Cp[i] = (c2)@(r,c),(c2)@(r,c+1)        4B -> LDS.32

#define H 256
#define W 256
#define HW (H * W)
#define BATCH 8
#define TX 64
#define TY 32
#define HALO 20
#define TDX (TX + 2 * HALO)      // 104
#define TDY (TY + 2 * HALO)      // 72
#define NTHREADS 512

__global__ __launch_bounds__(NTHREADS, 2)
void blurnet_kernel(const float* __restrict__ fake_S,
                    const float* __restrict__ blurmap,
                    const float* __restrict__ weight,
                    const float* __restrict__ bias,
                    float* __restrict__ out_fb,
                    float* __restrict__ out_off)
{
    extern __shared__ __align__(16) unsigned char smem_raw[];
    uint2*   Ap = (uint2*)smem_raw;                         // 72*104*8 = 59904 B
    __half2* Cp = (__half2*)(smem_raw + TDY * TDX * 8);     // 72*104*4 = 29952 B

    const int tx0 = blockIdx.x * TX;
    const int ty0 = blockIdx.y * TY;
    const int b   = blockIdx.z;
    const int tid = threadIdx.x;

    const float* img  = fake_S  + (size_t)b * 3 * HW;
    const float* bm   = blurmap + (size_t)b * 2 * HW;
    float*       fb   = out_fb  + (size_t)b * 3 * HW;
    float*       offp = out_off + (size_t)b * 30 * HW;

    // ---- Phase 1: halo fill (R3-style scalar loads) ----
    #pragma unroll 3
    for (int p = tid; p < TDY * TDX; p += NTHREADS) {
        int r  = p / TDX;
        int cc = p - r * TDX;
        int gy = ty0 - HALO + r;
        int gx = tx0 - HALO + cc;
        float v0 = 0.f, v1 = 0.f, v2 = 0.f;   // (gy, gx)
        float u0 = 0.f, u1 = 0.f, u2 = 0.f;   // (gy, gx+1)
        bool rowok = (unsigned)gy < (unsigned)H;
        if (rowok && (unsigned)gx < (unsigned)W) {
            int gi = gy * W + gx;
            v0 = __ldg(img + gi);
            v1 = __ldg(img + gi + HW);
            v2 = __ldg(img + gi + 2 * HW);
        }
        if (rowok && (unsigned)(gx + 1) < (unsigned)W) {
            int gi = gy * W + gx + 1;
            u0 = __ldg(img + gi);
            u1 = __ldg(img + gi + HW);
            u2 = __ldg(img + gi + 2 * HW);
        }
        __half2 lo = __floats2half2_rn(v0, v1);
        __half2 hi = __floats2half2_rn(u0, u1);
        uint2 w;
        w.x = *(unsigned int*)&lo;
        w.y = *(unsigned int*)&hi;
        Ap[p] = w;
        Cp[p] = __floats2half2_rn(v2, u2);
    }

    // ---- Phase 2: offsets output, vectorized (4 consecutive x / thread) ----
    {
        int ry = tid >> 4;            // 0..31
        int xq = (tid & 15) * 4;      // 0,4,...,60
        int gi = (ty0 + ry) * W + tx0 + xq;
        float4 b0 = *(const float4*)(bm + gi);
        float4 b1 = *(const float4*)(bm + gi + HW);
        float4 ob0 = make_float4(20.f * b0.x, 20.f * b0.y, 20.f * b0.z, 20.f * b0.w);
        float4 ob1 = make_float4(20.f * b1.x, 20.f * b1.y, 20.f * b1.z, 20.f * b1.w);
        #pragma unroll
        for (int k = 0; k < 15; k++) {
            const float t = (float)(7 - k) / 7.0f;
            float4 oy = make_float4(t * ob0.x, t * ob0.y, t * ob0.z, t * ob0.w);
            float4 ox = make_float4(t * ob1.x, t * ob1.y, t * ob1.z, t * ob1.w);
            *(float4*)(offp + (2 * k) * HW + gi)     = oy;
            *(float4*)(offp + (2 * k + 1) * HW + gi) = ox;
        }
    }
    __syncthreads();

    const float wgt = __ldg(weight) * (1.0f / 15.0f);
    const float bs  = __ldg(bias);

    // ---- Phase 3: blur, 4 pixels per thread (sequential) ----
    #pragma unroll 1
    for (int i = 0; i < (TX * TY) / NTHREADS; i++) {
        int p  = i * NTHREADS + tid;
        int yl = p >> 6;              // 0..31
        int xl = p & 63;              // 0..63
        int gy = ty0 + yl;
        int gx = tx0 + xl;
        int gidx = gy * W + gx;

        float ob0 = 20.0f * __ldg(bm + gidx);        // dy scale (ch0)
        float ob1 = 20.0f * __ldg(bm + gidx + HW);   // dx scale (ch1)

        // k = 7 (t = 0): exact center sample
        int cbase = (yl + HALO) * TDX + (xl + HALO);
        uint2 cw = Ap[cbase];
        float2 cl = __half22float2(*(__half2*)&cw.x);
        float2 cz = __half22float2(Cp[cbase]);
        float s0 = cl.x, s1 = cl.y, s2 = cz.x;

        #pragma unroll
        for (int k = 0; k < 15; k++) {
            if (k == 7) continue;
            const float t = (float)(7 - k) / 7.0f;   // compile-time constant
            float oy = t * ob0;
            float ox = t * ob1;

            float fy  = (float)gy + oy;              // global coords = ref rounding
            float fx  = (float)gx + ox;
            float fy0 = floorf(fy);
            float fx0 = floorf(fx);
            float tyf = fy - fy0;
            float txf = fx - fx0;
            int iy = (int)fy0 - ty0 + HALO;
            int ix = (int)fx0 - tx0 + HALO;
            int base2 = iy * TDX + ix;

            uint2   w0 = Ap[base2];           // row y0: (c0,c1)@x0,x1
            uint2   w1 = Ap[base2 + TDX];     // row y1
            __half2 z0 = Cp[base2];           // c2@(x0,x1), row y0
            __half2 z1 = Cp[base2 + TDX];     // row y1

            float2 p00 = __half22float2(*(__half2*)&w0.x);
            float2 p01 = __half22float2(*(__half2*)&w0.y);
            float2 p10 = __half22float2(*(__half2*)&w1.x);
            float2 p11 = __half22float2(*(__half2*)&w1.y);
            float2 q0  = __half22float2(z0);
            float2 q1  = __half22float2(z1);

            float w11f = tyf * txf;
            float w10f = tyf - w11f;
            float w01f = txf - w11f;
            float w00f = 1.0f - tyf - txf + w11f;

            s0 = fmaf(w00f, p00.x, s0); s0 = fmaf(w01f, p01.x, s0);
            s0 = fmaf(w10f, p10.x, s0); s0 = fmaf(w11f, p11.x, s0);
            s1 = fmaf(w00f, p00.y, s1); s1 = fmaf(w01f, p01.y, s1);
            s1 = fmaf(w10f, p10.y, s1); s1 = fmaf(w11f, p11.y, s1);
            s2 = fmaf(w00f, q0.x, s2);  s2 = fmaf(w01f, q0.y, s2);
            s2 = fmaf(w10f, q1.x, s2);  s2 = fmaf(w11f, q1.y, s2);
        }

        fb[gidx]          = fmaf(wgt, s0, bs);
        fb[gidx + HW]     = fmaf(wgt, s1, bs);
        fb[gidx + 2 * HW] = fmaf(wgt, s2, bs);
    }
}

extern "C" void kernel_launch(void* const* d_in, const int* in_sizes, int n_in,
                              void* d_out, int out_size)
{
    const float* fake_S  = (const float*)d_in[0];
    const float* blurmap = (const float*)d_in[1];
    const float* weight  = (const float*)d_in[2];
    const float* bias    = (const float*)d_in[3];

    float* out_fb  = (float*)d_out;
    float* out_off = (float*)d_out + (size_t)BATCH * 3 * HW;

    const int smem = TDY * TDX * 12;   // 89,856 B
    static bool configured = false;
    if (!configured) {
        cudaFuncSetAttribute(blurnet_kernel,
                             cudaFuncAttributeMaxDynamicSharedMemorySize, smem);
        configured = true;
    }

    dim3 grid(W / TX, H / TY, BATCH);   // (4, 8, 8) = 256 CTAs
    blurnet_kernel<<<grid, NTHREADS, smem>>>(fake_S, blurmap, weight, bias,
                                             out_fb, out_off);
}